// round 14
// baseline (speedup 1.0000x reference)
#include <cuda_runtime.h>

#define TJ 128          // block threads = j-tile = sort chunk
#define ITILE 2
#define TI (TJ * ITILE) // 256
#define MAXN 8192
#define NBINS 64
#define MAXCHUNK (MAXN / TJ)
#define MAX_BLOCKS 8192

__device__ float4 g_sorted[MAXN];
__device__ int    g_cnt[MAXCHUNK * NBINS];
__device__ int    g_off[MAXCHUNK * NBINS];
__device__ float  g_partials[MAX_BLOCKS];
__device__ int    g_counter = 0;
__device__ int    g_cntA = 0;
__device__ volatile int g_scanDone = 0;

// fs(d2) = 1 + s^2 P(s), s = sat((d2-9)/16); P(1) = -1 exactly -> far skip EXACT.
#define FS_A  1.733f
#define FS_B  (-23.203f)
#define FS_C  38.001f
#define FS_D  (-17.531f)

__device__ __forceinline__ int zbin(float z) {
    int b = (int)(z * (NBINS / 40.0f));
    return min(max(b, 0), NBINS - 1);
}

// ---- fused sort: 64 blocks; count+rank -> last block scans -> scatter ----
__global__ __launch_bounds__(TJ)
void sort_fused(const float* __restrict__ q, const float* __restrict__ xyz,
                int n, int nChunks) {
    const int bid = blockIdx.x, t = threadIdx.x;
    const int warp = t >> 5, lane = t & 31;
    __shared__ int warpCnt[TJ / 32][NBINS];
    __shared__ int warpBase[TJ / 32][NBINS];
    __shared__ int sBinTot[NBINS];
    __shared__ int sBinStart[NBINS];
    __shared__ int amLast;

    const int i = bid * TJ + t;
    float x = 0.f, y = 0.f, z = 0.f, wq = 0.f;
    int b = -1;
    for (int k2 = t; k2 < (TJ / 32) * NBINS; k2 += TJ)
        ((int*)warpCnt)[k2] = 0;
    __syncthreads();
    if (i < n) {
        x = xyz[3 * i]; y = xyz[3 * i + 1]; z = xyz[3 * i + 2]; wq = q[i];
        b = zbin(z);
    }
    unsigned mm = __match_any_sync(0xFFFFFFFFu, b);
    int rk = __popc(mm & ((1u << lane) - 1u));
    if (b >= 0 && rk == 0) warpCnt[warp][b] = __popc(mm);
    __syncthreads();
    if (t < NBINS) {
        int acc = 0;
        #pragma unroll
        for (int w2 = 0; w2 < TJ / 32; w2++) { warpBase[w2][t] = acc; acc += warpCnt[w2][t]; }
        g_cnt[bid * NBINS + t] = acc;
    }
    __syncthreads();
    int myRank = (b >= 0) ? (warpBase[warp][b] + rk) : 0;

    __threadfence();
    if (t == 0) amLast = (atomicAdd(&g_cntA, 1) == nChunks - 1) ? 1 : 0;
    __syncthreads();
    if (amLast) {
        if (t < NBINS) {
            int acc = 0;
            for (int blk = 0; blk < nChunks; blk++) {
                g_off[blk * NBINS + t] = acc;
                acc += g_cnt[blk * NBINS + t];
            }
            sBinTot[t] = acc;
        }
        __syncthreads();
        if (t == 0) {
            int s0 = 0;
            for (int k2 = 0; k2 < NBINS; k2++) { sBinStart[k2] = s0; s0 += sBinTot[k2]; }
        }
        __syncthreads();
        if (t < NBINS) {
            int s0 = sBinStart[t];
            for (int blk = 0; blk < nChunks; blk++)
                g_off[blk * NBINS + t] += s0;
        }
        __threadfence();
        __syncthreads();
        if (t == 0) { g_scanDone = 1; g_cntA = 0; }   // reset counter here
    } else {
        if (t == 0) { while (!g_scanDone) __nanosleep(32); }
        __syncthreads();
    }
    __threadfence();
    if (i < n)
        g_sorted[g_off[bid * NBINS + b] + myRank] = make_float4(x, y, z, wq);
    // g_scanDone reset by the pair kernel's final block (after all use).
}

// ---- pair kernel (identical to R11's measured-27.4us version) ----
__device__ __forceinline__ float term_d2(float d2) {
    float rinv = rsqrtf(d2);
    float s = __saturatef(fmaf(d2, 0.0625f, -0.5625f));
    float w = fmaf(fmaf(fmaf(FS_D, s, FS_C), s, FS_B), s, FS_A);
    float u = s * s;
    float isq = rsqrtf(d2 + 1.0f);
    float g = isq - rinv;
    float fs = fmaf(u, w, 1.0f);
    return fmaf(fs, g, rinv);
}

#define FARPAIR(m)                                                            \
    {                                                                         \
        float d2 = fmaf(nz##m, p.z, fmaf(ny##m, p.y,                          \
                     fmaf(nx##m, p.x, Ri##m + Rj)));                          \
        acc##m = fmaf(p.w, rsqrtf(d2), acc##m);                               \
    }

#define PAIR(m)                                                               \
    {                                                                         \
        float d2 = fmaf(nz##m, p.z, fmaf(ny##m, p.y,                          \
                     fmaf(nx##m, p.x, Ri##m + Rj)));                          \
        float rinv = rsqrtf(d2);                                              \
        acc##m = fmaf(p.w, rinv, acc##m);                                     \
        if (__any_sync(0xFFFFFFFFu, d2 < 25.0f)) {                            \
            float s = __saturatef(fmaf(d2, 0.0625f, -0.5625f));               \
            float w = fmaf(fmaf(fmaf(FS_D, s, FS_C), s, FS_B), s, FS_A);      \
            float u = s * s;                                                  \
            float fsw = u * w;                                                \
            float isq = rsqrtf(d2 + 1.0f);                                    \
            float g = isq - rinv;                                             \
            float corr = fmaf(fsw, g, g);                                     \
            acc##m = fmaf(p.w, corr, acc##m);                                 \
        }                                                                     \
    }

__global__ __launch_bounds__(TJ)
void elec_pair_kernel(float* __restrict__ out,
                      int n, int jT, int iT, int nBlocks) {
    const int bid = blockIdx.x;
    int d = 0, s = 0;
    for (;;) {
        int cnt = (jT - 1 - d) / ITILE + 1;
        if (cnt > iT) cnt = iT;
        if (cnt < 1) cnt = 1;
        if (bid < s + cnt) break;
        s += cnt; d++;
    }
    const int I = bid - s;
    const int J = ITILE * I + d;
    const int c = d;

    const int t = threadIdx.x;
    __shared__ float4 tile[TJ];
    __shared__ float  tileR[TJ];
    __shared__ float  warpsum[TJ / 32];
    __shared__ int    lastFlag;

    {
        const int jg = J * TJ + t;
        float4 p4 = (jg < n) ? g_sorted[jg]
                             : make_float4(1.0e6f + (float)t * 64.0f, 0.f, 0.f, 0.f);
        tile[t]  = p4;
        tileR[t] = fmaf(p4.x, p4.x, fmaf(p4.y, p4.y, p4.z * p4.z));
    }
    __syncthreads();

    const int ib = I * TI + t;
    float nx0, ny0, nz0, Ri0, qi0, nx1, ny1, nz1, Ri1, qi1;
    {
        #define LOADI(m, ig)                                                      \
            { float4 a = ((ig) < n) ? g_sorted[(ig)]                              \
                  : make_float4(2.0e6f + (float)(ig) * 64.0f, 0.f, 0.f, 0.f);     \
              nx##m = -2.0f * a.x; ny##m = -2.0f * a.y; nz##m = -2.0f * a.z;      \
              Ri##m = fmaf(a.x, a.x, fmaf(a.y, a.y, a.z * a.z));                  \
              qi##m = a.w; }
        LOADI(0, ib) LOADI(1, ib + TJ)
        #undef LOADI
    }

    float acc0 = 0.0f, acc1 = 0.0f, accD = 0.0f;

    if (c >= ITILE) {
        int iLast  = min(I * TI + TI, n) - 1;
        int jFirst = min(J * TJ, n - 1);
        bool nearBlk = (g_sorted[jFirst].z - g_sorted[iLast].z) < 5.0f;
        if (!nearBlk) {
            #pragma unroll 4
            for (int k = 0; k < TJ; k++) {
                float4 p = tile[k]; float Rj = tileR[k];
                FARPAIR(0) FARPAIR(1)
            }
        } else {
            #pragma unroll 4
            for (int k = 0; k < TJ; k++) {
                float4 p = tile[k]; float Rj = tileR[k];
                PAIR(0) PAIR(1)
            }
        }
    } else {
        if (c == 1) {
            #pragma unroll 4
            for (int k = 0; k < TJ; k++) {
                float4 p = tile[k]; float Rj = tileR[k];
                PAIR(0)
            }
        }
        float nxd = (c == 0) ? nx0 : nx1;
        float nyd = (c == 0) ? ny0 : ny1;
        float nzd = (c == 0) ? nz0 : nz1;
        float Rid = (c == 0) ? Ri0 : Ri1;
        for (int k = t + 1; k < TJ; k++) {
            float4 p = tile[k];
            float Rj = tileR[k];
            float d2 = fmaf(nzd, p.z, fmaf(nyd, p.y, fmaf(nxd, p.x, Rid + Rj)));
            accD = fmaf(p.w, term_d2(d2), accD);
        }
    }

    float qd = (c >= ITILE) ? 0.0f : (c == 0) ? qi0 : qi1;
    float accT = qi0 * acc0 + qi1 * acc1 + qd * accD;

    #pragma unroll
    for (int off = 16; off > 0; off >>= 1)
        accT += __shfl_down_sync(0xFFFFFFFFu, accT, off);
    if ((t & 31) == 0) warpsum[t >> 5] = accT;
    __syncthreads();

    if (t == 0) {
        float sum = 0.0f;
        #pragma unroll
        for (int w2 = 0; w2 < TJ / 32; w2++) sum += warpsum[w2];
        g_partials[bid] = sum;
        __threadfence();
        int ticket = atomicAdd(&g_counter, 1);
        lastFlag = (ticket == nBlocks - 1) ? 1 : 0;
    }
    __syncthreads();

    if (lastFlag) {
        float a2 = 0.0f;
        for (int i2 = t; i2 < nBlocks; i2 += TJ)
            a2 += g_partials[i2];
        #pragma unroll
        for (int off = 16; off > 0; off >>= 1)
            a2 += __shfl_down_sync(0xFFFFFFFFu, a2, off);
        if ((t & 31) == 0) warpsum[t >> 5] = a2;
        __syncthreads();
        if (t == 0) {
            float sum = 0.0f;
            #pragma unroll
            for (int w2 = 0; w2 < TJ / 32; w2++) sum += warpsum[w2];
            out[0] = sum * 332.0637f;
            g_counter = 0;
            g_scanDone = 0;   // reset sort flag for next replay
        }
    }
}

extern "C" void kernel_launch(void* const* d_in, const int* in_sizes, int n_in,
                              void* d_out, int out_size) {
    const float* q   = (const float*)d_in[0];
    const float* xyz = (const float*)d_in[1];
    float* out = (float*)d_out;

    int n = in_sizes[0];
    if (n > MAXN) n = MAXN;
    int nChunks = (n + TJ - 1) / TJ;
    int jT = (n + TJ - 1) / TJ;
    int iT = (n + TI - 1) / TI;

    int nBlocks = 0;
    for (int d = 0; d < jT; d++) {
        int cnt = (jT - 1 - d) / ITILE + 1;
        if (cnt > iT) cnt = iT;
        if (cnt < 1) cnt = 1;
        nBlocks += cnt;
    }
    if (nBlocks > MAX_BLOCKS) nBlocks = MAX_BLOCKS;

    sort_fused<<<nChunks, TJ>>>(q, xyz, n, nChunks);
    elec_pair_kernel<<<nBlocks, TJ>>>(out, n, jT, iT, nBlocks);
}

// round 16
// speedup vs baseline: 1.3575x; 1.3575x over previous
#include <cuda_runtime.h>

#define TJ 128          // pair-kernel block threads = j-tile
#define ITILE 2
#define TI (TJ * ITILE) // 256
#define SCH 512         // sort chunk size (threads per sort block)
#define MAXN 8192
#define NBINS 64
#define NCH (MAXN / SCH)    // 16 sort chunks
#define MAX_BLOCKS 8192

__device__ float4 g_sorted[MAXN];
__device__ int    g_cnt[NCH * NBINS];
__device__ int    g_off[NCH * NBINS];
__device__ float  g_partials[MAX_BLOCKS];
__device__ int    g_counter = 0;
__device__ int    g_cntA = 0;
__device__ volatile int g_scanDone = 0;

// fs(d2) = 1 + s^2 P(s), s = sat((d2-9)/16); P(1) = -1 exactly -> far skip EXACT.
#define FS_A  1.733f
#define FS_B  (-23.203f)
#define FS_C  38.001f
#define FS_D  (-17.531f)

__device__ __forceinline__ int zbin(float z) {
    int b = (int)(z * (NBINS / 40.0f));
    return min(max(b, 0), NBINS - 1);
}

// ---- fused sort: 16 blocks x 512 thr; count+rank -> smem scan -> scatter ----
__global__ __launch_bounds__(SCH)
void sort_fused(const float* __restrict__ q, const float* __restrict__ xyz,
                int n, int nChunks) {
    const int bid = blockIdx.x, t = threadIdx.x;
    const int warp = t >> 5, lane = t & 31;
    const int NW = SCH / 32;   // 16 warps

    __shared__ int warpCnt[NW][NBINS];    // reused as sAll in scan phase
    __shared__ int warpBase[NW][NBINS];   // reused as sOff in scan phase
    __shared__ int sTot[NBINS];
    __shared__ int sStart[NBINS];
    __shared__ int amLast;

    const int i = bid * SCH + t;
    float x = 0.f, y = 0.f, z = 0.f, wq = 0.f;
    int b = -1;
    for (int k2 = t; k2 < NW * NBINS; k2 += SCH)
        ((int*)warpCnt)[k2] = 0;
    __syncthreads();
    if (i < n) {
        x = xyz[3 * i]; y = xyz[3 * i + 1]; z = xyz[3 * i + 2]; wq = q[i];
        b = zbin(z);
    }
    unsigned mm = __match_any_sync(0xFFFFFFFFu, b);
    int rk = __popc(mm & ((1u << lane) - 1u));
    if (b >= 0 && rk == 0) warpCnt[warp][b] = __popc(mm);
    __syncthreads();
    if (t < NBINS) {
        int acc = 0;
        #pragma unroll
        for (int w2 = 0; w2 < NW; w2++) { warpBase[w2][t] = acc; acc += warpCnt[w2][t]; }
        g_cnt[bid * NBINS + t] = acc;
    }
    __syncthreads();
    const int myRank = (b >= 0) ? (warpBase[warp][b] + rk) : 0;
    __syncthreads();   // warpCnt/warpBase free for reuse after this point

    __threadfence();
    if (t == 0) amLast = (atomicAdd(&g_cntA, 1) == nChunks - 1) ? 1 : 0;
    __syncthreads();

    if (amLast) {
        int* sAll = (int*)warpCnt;     // [nChunks*NBINS] <= 1024
        int* sOff = (int*)warpBase;
        // bulk coalesced load of all counts (independent loads, MLP-hidden)
        for (int idx = t; idx < nChunks * NBINS; idx += SCH)
            sAll[idx] = g_cnt[idx];
        __syncthreads();
        if (t < NBINS) {
            int acc = 0;
            for (int blk = 0; blk < nChunks; blk++) {
                sOff[blk * NBINS + t] = acc;
                acc += sAll[blk * NBINS + t];
            }
            sTot[t] = acc;
        }
        __syncthreads();
        if (t == 0) {
            int s0 = 0;
            for (int k2 = 0; k2 < NBINS; k2++) { sStart[k2] = s0; s0 += sTot[k2]; }
        }
        __syncthreads();
        if (t < NBINS) {
            int s0 = sStart[t];
            for (int blk = 0; blk < nChunks; blk++)
                g_off[blk * NBINS + t] = sOff[blk * NBINS + t] + s0;
        }
        __threadfence();
        __syncthreads();
        if (t == 0) { g_cntA = 0; g_scanDone = 1; }
    } else {
        if (t == 0) { while (!g_scanDone) __nanosleep(32); }
        __syncthreads();
    }
    __threadfence();

    if (i < n)
        g_sorted[g_off[bid * NBINS + b] + myRank] = make_float4(x, y, z, wq);
    // g_scanDone reset by the pair kernel's final block.
}

// ---- pair kernel ----
__device__ __forceinline__ float term_d2(float d2) {
    float rinv = rsqrtf(d2);
    float s = __saturatef(fmaf(d2, 0.0625f, -0.5625f));
    float w = fmaf(fmaf(fmaf(FS_D, s, FS_C), s, FS_B), s, FS_A);
    float u = s * s;
    float isq = rsqrtf(d2 + 1.0f);
    float g = isq - rinv;
    float fs = fmaf(u, w, 1.0f);
    return fmaf(fs, g, rinv);
}

#define FARPAIR(m)                                                            \
    {                                                                         \
        float d2 = fmaf(nz##m, p.z, fmaf(ny##m, p.y,                          \
                     fmaf(nx##m, p.x, Ri##m + Rj)));                          \
        acc##m = fmaf(p.w, rsqrtf(d2), acc##m);                               \
    }

// Near path: branchless full term (no vote, no divergence).
#define NPAIR(m)                                                              \
    {                                                                         \
        float d2 = fmaf(nz##m, p.z, fmaf(ny##m, p.y,                          \
                     fmaf(nx##m, p.x, Ri##m + Rj)));                          \
        acc##m = fmaf(p.w, term_d2(d2), acc##m);                              \
    }

__global__ __launch_bounds__(TJ)
void elec_pair_kernel(float* __restrict__ out,
                      int n, int jT, int iT, int nBlocks) {
    const int bid = blockIdx.x;
    int d = 0, s = 0;
    for (;;) {
        int cnt = (jT - 1 - d) / ITILE + 1;
        if (cnt > iT) cnt = iT;
        if (cnt < 1) cnt = 1;
        if (bid < s + cnt) break;
        s += cnt; d++;
    }
    const int I = bid - s;
    const int J = ITILE * I + d;
    const int c = d;

    const int t = threadIdx.x;
    __shared__ float4 tile[TJ];
    __shared__ float  tileR[TJ];
    __shared__ float  warpsum[TJ / 32];
    __shared__ int    lastFlag;

    {
        const int jg = J * TJ + t;
        float4 p4 = (jg < n) ? g_sorted[jg]
                             : make_float4(1.0e6f + (float)t * 64.0f, 0.f, 0.f, 0.f);
        tile[t]  = p4;
        tileR[t] = fmaf(p4.x, p4.x, fmaf(p4.y, p4.y, p4.z * p4.z));
    }
    __syncthreads();

    const int ib = I * TI + t;
    float nx0, ny0, nz0, Ri0, qi0, nx1, ny1, nz1, Ri1, qi1;
    {
        #define LOADI(m, ig)                                                      \
            { float4 a = ((ig) < n) ? g_sorted[(ig)]                              \
                  : make_float4(2.0e6f + (float)(ig) * 64.0f, 0.f, 0.f, 0.f);     \
              nx##m = -2.0f * a.x; ny##m = -2.0f * a.y; nz##m = -2.0f * a.z;      \
              Ri##m = fmaf(a.x, a.x, fmaf(a.y, a.y, a.z * a.z));                  \
              qi##m = a.w; }
        LOADI(0, ib) LOADI(1, ib + TJ)
        #undef LOADI
    }

    float acc0 = 0.0f, acc1 = 0.0f, accD = 0.0f;

    if (c >= ITILE) {
        int iLast  = min(I * TI + TI, n) - 1;
        int jFirst = min(J * TJ, n - 1);
        bool nearBlk = (g_sorted[jFirst].z - g_sorted[iLast].z) < 5.0f;
        if (!nearBlk) {
            #pragma unroll 4
            for (int k = 0; k < TJ; k++) {
                float4 p = tile[k]; float Rj = tileR[k];
                FARPAIR(0) FARPAIR(1)
            }
        } else {
            #pragma unroll 4
            for (int k = 0; k < TJ; k++) {
                float4 p = tile[k]; float Rj = tileR[k];
                NPAIR(0) NPAIR(1)
            }
        }
    } else {
        if (c == 1) {
            #pragma unroll 4
            for (int k = 0; k < TJ; k++) {
                float4 p = tile[k]; float Rj = tileR[k];
                NPAIR(0)
            }
        }
        float nxd = (c == 0) ? nx0 : nx1;
        float nyd = (c == 0) ? ny0 : ny1;
        float nzd = (c == 0) ? nz0 : nz1;
        float Rid = (c == 0) ? Ri0 : Ri1;
        for (int k = t + 1; k < TJ; k++) {
            float4 p = tile[k];
            float Rj = tileR[k];
            float d2 = fmaf(nzd, p.z, fmaf(nyd, p.y, fmaf(nxd, p.x, Rid + Rj)));
            accD = fmaf(p.w, term_d2(d2), accD);
        }
    }

    float qd = (c >= ITILE) ? 0.0f : (c == 0) ? qi0 : qi1;
    float accT = qi0 * acc0 + qi1 * acc1 + qd * accD;

    #pragma unroll
    for (int off = 16; off > 0; off >>= 1)
        accT += __shfl_down_sync(0xFFFFFFFFu, accT, off);
    if ((t & 31) == 0) warpsum[t >> 5] = accT;
    __syncthreads();

    if (t == 0) {
        float sum = 0.0f;
        #pragma unroll
        for (int w2 = 0; w2 < TJ / 32; w2++) sum += warpsum[w2];
        g_partials[bid] = sum;
        __threadfence();
        int ticket = atomicAdd(&g_counter, 1);
        lastFlag = (ticket == nBlocks - 1) ? 1 : 0;
    }
    __syncthreads();

    if (lastFlag) {
        float a2 = 0.0f;
        for (int i2 = t; i2 < nBlocks; i2 += TJ)
            a2 += g_partials[i2];
        #pragma unroll
        for (int off = 16; off > 0; off >>= 1)
            a2 += __shfl_down_sync(0xFFFFFFFFu, a2, off);
        if ((t & 31) == 0) warpsum[t >> 5] = a2;
        __syncthreads();
        if (t == 0) {
            float sum = 0.0f;
            #pragma unroll
            for (int w2 = 0; w2 < TJ / 32; w2++) sum += warpsum[w2];
            out[0] = sum * 332.0637f;
            g_counter = 0;
            g_scanDone = 0;   // reset sort flag for next replay
        }
    }
}

extern "C" void kernel_launch(void* const* d_in, const int* in_sizes, int n_in,
                              void* d_out, int out_size) {
    const float* q   = (const float*)d_in[0];
    const float* xyz = (const float*)d_in[1];
    float* out = (float*)d_out;

    int n = in_sizes[0];
    if (n > MAXN) n = MAXN;
    int nChunks = (n + SCH - 1) / SCH;
    int jT = (n + TJ - 1) / TJ;
    int iT = (n + TI - 1) / TI;

    int nBlocks = 0;
    for (int d = 0; d < jT; d++) {
        int cnt = (jT - 1 - d) / ITILE + 1;
        if (cnt > iT) cnt = iT;
        if (cnt < 1) cnt = 1;
        nBlocks += cnt;
    }
    if (nBlocks > MAX_BLOCKS) nBlocks = MAX_BLOCKS;

    sort_fused<<<nChunks, SCH>>>(q, xyz, n, nChunks);
    elec_pair_kernel<<<nBlocks, TJ>>>(out, n, jT, iT, nBlocks);
}